// round 16
// baseline (speedup 1.0000x reference)
#include <cuda_runtime.h>
#include <cuda_fp16.h>
#include <math.h>
#include <stdint.h>

#define BB 8
#define CC 256
#define NN 2048

// tile-major pre-swizzled splits: [b][blk(16)][kc(4)][s(2)][16KB tile]
__device__ __align__(128) __half g_xs[(size_t)BB * NN * 512];
__device__ __align__(16) float g_xt[(size_t)BB * NN * CC];
__device__ unsigned long long g_key[BB * NN];

#define SWZ(o) ((o) ^ (((o) >> 3) & 0x70))
#define BLK_BYTES 131072

// 24 strips (it<<4 | jt0), <=8 tiles each, sorted by length descending
__device__ const unsigned char g_strips[24] = {
    0x00, 0x08, 0x11, 0x22, 0x33, 0x44, 0x55, 0x66, 0x77, 0x88,   // 8-tile
    0x19, 0x99,                                                   // 7
    0x2A, 0xAA,                                                   // 6
    0x3B, 0xBB,                                                   // 5
    0x4C, 0xCC,                                                   // 4
    0x5D, 0xDD,                                                   // 3
    0x6E, 0xEE,                                                   // 2
    0x7F, 0xFF                                                    // 1
};

// ---------------------------------------------------------------------------
// prep: rn + f32 transpose + rn-scaled 2-way fp16 splits written tile-major
// swizzled. grid (NN/32, BB), 256 threads.
// ---------------------------------------------------------------------------
__global__ __launch_bounds__(256) void prep_kernel(const float* __restrict__ x) {
    __shared__ __half S[32][520];
    __shared__ float nsum[32][8];
    __shared__ float rns[32];
    int b = blockIdx.y, n0 = blockIdx.x * 32;
    int tid = threadIdx.x, nl = tid & 31, c8 = tid >> 5;
    const float* xp = x + (size_t)b * CC * NN + n0 + nl;

    float v[32];
    float s = 0.f;
#pragma unroll
    for (int cc = 0; cc < 32; ++cc) {
        int c = c8 * 32 + cc;
        v[cc] = xp[(size_t)c * NN];
        s = fmaf(v[cc], v[cc], s);
    }
    nsum[nl][c8] = s;
    __syncthreads();
    if (tid < 32) {
        float t = 0.f;
#pragma unroll
        for (int q = 0; q < 8; ++q) t += nsum[tid][q];
        rns[tid] = rsqrtf(t + (float)CC * 1e-6f);
    }
    __syncthreads();
    float rn = rns[nl];

    float* xt = g_xt + ((size_t)(b * NN + n0 + nl)) * 256 + c8 * 32;
#pragma unroll
    for (int q = 0; q < 8; ++q)
        *(float4*)(xt + q * 4) = make_float4(v[q * 4], v[q * 4 + 1], v[q * 4 + 2], v[q * 4 + 3]);

#pragma unroll
    for (int cc = 0; cc < 32; ++cc) {
        int c = c8 * 32 + cc;
        float f = v[cc] * rn;
        __half h1 = __float2half_rn(f);
        float r1 = f - __half2float(h1);
        __half h2 = __float2half_rn(r1);
        S[nl][c] = h1; S[nl][256 + c] = h2;
    }
    __syncthreads();

    char* outb = (char*)g_xs + (size_t)b * (NN / 128) * BLK_BYTES
               + (size_t)(n0 >> 7) * BLK_BYTES;
    int row0 = n0 & 127;
#pragma unroll
    for (int r = 0; r < 8; ++r) {
        int idx = tid + r * 256;
        int row32 = idx >> 6, c = idx & 63;
        int s2 = c >> 5, cc = c & 31;
        int kc = cc >> 3, c16 = cc & 7;
        uint4 val = *(const uint4*)&S[row32][s2 * 256 + kc * 64 + c16 * 8];
        *(uint4*)(outb + (kc * 2 + s2) * 16384 +
                  SWZ((row0 + row32) * 128 + c16 * 16)) = val;
    }
}

// ---------------------------------------------------------------------------
// smem map: A 8 tiles at 0 (128KB); ring 2x32KB at 131072; merge; bars
// ---------------------------------------------------------------------------
#define RINGOFF 131072
#define RVOFF   196608                 // [3][128] f32
#define RJOFF   198144                 // [3][128] i32
#define CVOFF   199680
#define CJOFF   201216
#define BAR_A   202752
#define BAR_R   202760
#define SMEM_TOTAL 202880

__device__ __forceinline__ void ldsm4(uint32_t* r, uint32_t saddr) {
    asm volatile("ldmatrix.sync.aligned.m8n8.x4.shared.b16 {%0,%1,%2,%3}, [%4];"
                 : "=r"(r[0]), "=r"(r[1]), "=r"(r[2]), "=r"(r[3]) : "r"(saddr));
}
__device__ __forceinline__ void mma16816f(float (&d)[4], const uint32_t (&a)[4],
                                          uint32_t b0, uint32_t b1) {
    asm volatile(
        "mma.sync.aligned.m16n8k16.row.col.f32.f16.f16.f32 "
        "{%0,%1,%2,%3},{%4,%5,%6,%7},{%8,%9},{%0,%1,%2,%3};"
        : "+f"(d[0]), "+f"(d[1]), "+f"(d[2]), "+f"(d[3])
        : "r"(a[0]), "r"(a[1]), "r"(a[2]), "r"(a[3]), "r"(b0), "r"(b1));
}
__device__ __forceinline__ void mma16816h(uint32_t (&d)[2], const uint32_t (&a)[4],
                                          uint32_t b0, uint32_t b1) {
    asm volatile(
        "mma.sync.aligned.m16n8k16.row.col.f16.f16.f16.f16 "
        "{%0,%1},{%2,%3,%4,%5},{%6,%7},{%0,%1};"
        : "+r"(d[0]), "+r"(d[1])
        : "r"(a[0]), "r"(a[1]), "r"(a[2]), "r"(a[3]), "r"(b0), "r"(b1));
}
__device__ __forceinline__ unsigned long long packKey(float v, int idx) {
    uint32_t u = __float_as_uint(v);
    uint32_t key = (u & 0x80000000u) ? ~u : (u | 0x80000000u);
    return ((unsigned long long)key << 32) | (uint32_t)(0xFFFFFFFFu - (uint32_t)idx);
}

__device__ __forceinline__ void mbar_init(uint32_t a) {
    asm volatile("mbarrier.init.shared.b64 [%0], 1;" :: "r"(a) : "memory");
}
__device__ __forceinline__ void mbar_expect(uint32_t a, uint32_t bytes) {
    asm volatile("mbarrier.arrive.expect_tx.shared.b64 _, [%0], %1;"
                 :: "r"(a), "r"(bytes) : "memory");
}
__device__ __forceinline__ void bulk_cp(uint32_t sdst, const void* gsrc,
                                        uint32_t bytes, uint32_t bar) {
    asm volatile(
        "cp.async.bulk.shared::cta.global.mbarrier::complete_tx::bytes "
        "[%0], [%1], %2, [%3];"
        :: "r"(sdst), "l"(gsrc), "r"(bytes), "r"(bar) : "memory");
}
__device__ __forceinline__ void mbar_wait(uint32_t a, uint32_t ph) {
    uint32_t done;
    do {
        asm volatile(
            "{\n\t.reg .pred p;\n\t"
            "mbarrier.try_wait.parity.acquire.cta.shared::cta.b64 p, [%1], %2, 0x989680;\n\t"
            "selp.b32 %0, 1, 0, p;\n\t}"
            : "=r"(done) : "r"(a), "r"(ph) : "memory");
    } while (!done);
}

// ---------------------------------------------------------------------------
// simargmax: triangular strips of <=8 j-tiles (longest-first), TMA bulk-copy
// transport, 512 threads = 16 warps (4M x 4N), 32x32 per-warp tile.
// grid (24, BB).
// ---------------------------------------------------------------------------
__global__ __launch_bounds__(512, 1) void simargmax_kernel() {
    extern __shared__ __align__(1024) char sm[];
    const int b = blockIdx.y;
    const int sv = g_strips[blockIdx.x];
    const int it = sv >> 4, jt0 = sv & 15;
    const int ntiles = min(8, 16 - jt0);
    const int i0 = it * 128;
    const int N = ntiles * 4;

    const int tid = threadIdx.x, lane = tid & 31, wid = tid >> 5;
    const int wm = wid >> 2, wn = wid & 3;
    const uint32_t smb = (uint32_t)__cvta_generic_to_shared(sm);
    const char* xsb = (const char*)g_xs + (size_t)b * 16 * BLK_BYTES;

    if (tid == 0) {
        mbar_init(smb + BAR_A);
        mbar_init(smb + BAR_R);
        mbar_init(smb + BAR_R + 8);
    }
    __syncthreads();
    if (tid == 0) {
        mbar_expect(smb + BAR_A, BLK_BYTES);
        bulk_cp(smb, xsb + (size_t)it * BLK_BYTES, BLK_BYTES, smb + BAR_A);
        mbar_expect(smb + BAR_R, 32768);
        bulk_cp(smb + RINGOFF, xsb + (size_t)jt0 * BLK_BYTES, 32768, smb + BAR_R);
    }

    const int ar0 = wm * 32 + (lane & 15);
    const int akh = lane >> 4;
    const int jr0 = wn * 32 + ((lane >> 4) & 1) * 8 + (lane & 7);
    const int bkh = (lane >> 3) & 1;

    const float NEG = __int_as_float(0xff800000);
    float rbv[4]; int rbj[4];
#pragma unroll
    for (int s = 0; s < 4; ++s) { rbv[s] = NEG; rbj[s] = 0; }

    float* Rv = (float*)(sm + RVOFF);  int* Rj = (int*)(sm + RJOFF);
    float* Cv = (float*)(sm + CVOFF);  int* Cj = (int*)(sm + CJOFF);

    for (int tile = 0; tile < ntiles; ++tile) {
        const int jt = jt0 + tile;
        const int j0 = jt * 128;
        const bool diag = (jt == it);

        float    acc[2][4][4];
        uint32_t accH[2][4][2];
#pragma unroll
        for (int mt = 0; mt < 2; ++mt)
#pragma unroll
            for (int nt = 0; nt < 4; ++nt) {
#pragma unroll
                for (int rr = 0; rr < 4; ++rr) acc[mt][nt][rr] = 0.f;
                accH[mt][nt][0] = 0u; accH[mt][nt][1] = 0u;
            }

        for (int kcc = 0; kcc < 4; ++kcc) {
            const int g = tile * 4 + kcc;
            const int slot = g & 1;
            mbar_wait(smb + BAR_R + slot * 8, (g >> 1) & 1);
            if (g == 0) mbar_wait(smb + BAR_A, 0);
            __syncthreads();
            if (tid == 0 && g + 1 < N) {
                const int g1 = g + 1;
                const int jb1 = jt0 + (g1 >> 2), kc1 = g1 & 3;
                mbar_expect(smb + BAR_R + (g1 & 1) * 8, 32768);
                bulk_cp(smb + RINGOFF + (g1 & 1) * 32768,
                        xsb + (size_t)jb1 * BLK_BYTES + kc1 * 32768,
                        32768, smb + BAR_R + (g1 & 1) * 8);
            }

#pragma unroll
            for (int ks = 0; ks < 4; ++ks) {
                uint32_t bf0[2][4], bf1[2][4];
#pragma unroll
                for (int ntp = 0; ntp < 2; ++ntp) {
                    int ro = (jr0 + ntp * 16) * 128 + (ks * 2 + bkh) * 16;
                    ldsm4(bf0[ntp], smb + RINGOFF + slot * 32768 + SWZ(ro));
                    ldsm4(bf1[ntp], smb + RINGOFF + slot * 32768 + 16384 + SWZ(ro));
                }
                uint32_t a0[2][4], a1[2][4];
#pragma unroll
                for (int mt = 0; mt < 2; ++mt) {
                    int ro = (ar0 + mt * 16) * 128 + (ks * 2 + akh) * 16;
                    ldsm4(a0[mt], smb + (kcc * 2) * 16384 + SWZ(ro));
                    ldsm4(a1[mt], smb + (kcc * 2 + 1) * 16384 + SWZ(ro));
                }
#pragma unroll
                for (int ntp = 0; ntp < 2; ++ntp) {
                    mma16816f(acc[0][ntp * 2],     a0[0], bf0[ntp][0], bf0[ntp][1]);
                    mma16816f(acc[0][ntp * 2 + 1], a0[0], bf0[ntp][2], bf0[ntp][3]);
                    mma16816f(acc[1][ntp * 2],     a0[1], bf0[ntp][0], bf0[ntp][1]);
                    mma16816f(acc[1][ntp * 2 + 1], a0[1], bf0[ntp][2], bf0[ntp][3]);
                    mma16816h(accH[0][ntp * 2],     a1[0], bf0[ntp][0], bf0[ntp][1]);
                    mma16816h(accH[0][ntp * 2 + 1], a1[0], bf0[ntp][2], bf0[ntp][3]);
                    mma16816h(accH[1][ntp * 2],     a1[1], bf0[ntp][0], bf0[ntp][1]);
                    mma16816h(accH[1][ntp * 2 + 1], a1[1], bf0[ntp][2], bf0[ntp][3]);
                    mma16816h(accH[0][ntp * 2],     a0[0], bf1[ntp][0], bf1[ntp][1]);
                    mma16816h(accH[0][ntp * 2 + 1], a0[0], bf1[ntp][2], bf1[ntp][3]);
                    mma16816h(accH[1][ntp * 2],     a0[1], bf1[ntp][0], bf1[ntp][1]);
                    mma16816h(accH[1][ntp * 2 + 1], a0[1], bf1[ntp][2], bf1[ntp][3]);
                }
            }
        }

        // ---- per-tile epilogue ----
        float cbv[8]; int cbi[8];
#pragma unroll
        for (int s = 0; s < 8; ++s) { cbv[s] = NEG; cbi[s] = 0; }

#pragma unroll
        for (int mt = 0; mt < 2; ++mt)
#pragma unroll
            for (int nt = 0; nt < 4; ++nt)
#pragma unroll
                for (int rr = 0; rr < 4; ++rr) {
                    int jl = wn * 32 + nt * 8 + (lane & 3) * 2 + (rr & 1);
                    int il = wm * 32 + mt * 16 + (rr >> 1) * 8 + (lane >> 2);
                    __half2 h2 = *(__half2*)&accH[mt][nt][rr >> 1];
                    float cross = (rr & 1) ? __high2float(h2) : __low2float(h2);
                    float v = acc[mt][nt][rr] + cross;
                    if (diag && il == jl) v = NEG;
                    int slot = mt * 2 + (rr >> 1);
                    if (v > rbv[slot]) { rbv[slot] = v; rbj[slot] = j0 + jl; }
                    int ci = nt * 2 + (rr & 1);
                    if (v > cbv[ci]) { cbv[ci] = v; cbi[ci] = il; }
                }

        if (!diag) {
#pragma unroll
            for (int ci = 0; ci < 8; ++ci) {
                float v = cbv[ci]; int i = cbi[ci];
#pragma unroll
                for (int o = 4; o <= 16; o <<= 1) {
                    float vo = __shfl_xor_sync(0xffffffffu, v, o);
                    int   io = __shfl_xor_sync(0xffffffffu, i, o);
                    if (vo > v || (vo == v && io < i)) { v = vo; i = io; }
                }
                cbv[ci] = v; cbi[ci] = i;
                if (wm > 0 && lane < 4) {
                    int col = wn * 32 + (ci >> 1) * 8 + lane * 2 + (ci & 1);
                    Cv[(wm - 1) * 128 + col] = v;
                    Cj[(wm - 1) * 128 + col] = i;
                }
            }
            __syncthreads();
            if (wm == 0 && lane < 4) {
#pragma unroll
                for (int ci = 0; ci < 8; ++ci) {
                    int col = wn * 32 + (ci >> 1) * 8 + lane * 2 + (ci & 1);
                    float v = cbv[ci]; int i = cbi[ci];
#pragma unroll
                    for (int w = 0; w < 3; ++w) {
                        float vo = Cv[w * 128 + col];
                        int   io = Cj[w * 128 + col];
                        if (vo > v || (vo == v && io < i)) { v = vo; i = io; }
                    }
                    atomicMax(&g_key[b * NN + j0 + col], packKey(v, i0 + i));
                }
            }
            __syncthreads();
        }
    }

    // ---- strip end: row reduce (quad shfl + 4 wn-warps via smem) + atomics ----
#pragma unroll
    for (int slot = 0; slot < 4; ++slot) {
        float v = rbv[slot]; int j = rbj[slot];
#pragma unroll
        for (int o = 1; o <= 2; o <<= 1) {
            float vo = __shfl_xor_sync(0xffffffffu, v, o);
            int   jo = __shfl_xor_sync(0xffffffffu, j, o);
            if (vo > v || (vo == v && jo < j)) { v = vo; j = jo; }
        }
        rbv[slot] = v; rbj[slot] = j;
        int row = wm * 32 + (slot >> 1) * 16 + (slot & 1) * 8 + (lane >> 2);
        if (wn > 0 && (lane & 3) == 0) {
            Rv[(wn - 1) * 128 + row] = v;
            Rj[(wn - 1) * 128 + row] = j;
        }
    }
    __syncthreads();
    if (wn == 0 && (lane & 3) == 0) {
#pragma unroll
        for (int slot = 0; slot < 4; ++slot) {
            int row = wm * 32 + (slot >> 1) * 16 + (slot & 1) * 8 + (lane >> 2);
            float v = rbv[slot]; int j = rbj[slot];
#pragma unroll
            for (int w = 0; w < 3; ++w) {
                float vo = Rv[w * 128 + row];
                int   jo = Rj[w * 128 + row];
                if (vo > v || (vo == v && jo < j)) { v = vo; j = jo; }
            }
            atomicMax(&g_key[b * NN + i0 + row], packKey(v, j));
        }
    }
}

// ---------------------------------------------------------------------------
// fuse
// ---------------------------------------------------------------------------
#define FS_SF 32896
#define FS_W  65792
#define FS_JI 69888
#define FS_W0 70016
#define FS_W1 70144
#define FS_TOTAL 70272

__global__ __launch_bounds__(256) void fuse_kernel(const float* __restrict__ W,
                                                   float* __restrict__ out) {
    extern __shared__ char fsm[];
    float* Sx  = (float*)fsm;
    float* Sf  = (float*)(fsm + FS_SF);
    float* Wsh = (float*)(fsm + FS_W);
    int*   Ji  = (int*)(fsm + FS_JI);
    float* W0  = (float*)(fsm + FS_W0);
    float* W1  = (float*)(fsm + FS_W1);

    int b = blockIdx.y, n0 = blockIdx.x * 32, tid = threadIdx.x;
    for (int e = tid; e < 1024; e += 256) Wsh[e] = W[e];
    if (tid < 32) {
        unsigned long long k = g_key[b * NN + n0 + tid];
        Ji[tid] = (int)(0xFFFFFFFFu - (uint32_t)(k & 0xFFFFFFFFu));
    }
    __syncthreads();

    const float* xtb = g_xt + (size_t)b * NN * 256;
    {
        int r = tid >> 3, p = tid & 7;
        const float* srcx = xtb + (size_t)(n0 + r) * 256 + p * 32;
        const float* srcf = xtb + (size_t)Ji[r] * 256 + p * 32;
#pragma unroll
        for (int q = 0; q < 8; ++q) {
            float4 a = *(const float4*)(srcx + q * 4);
            float4 c = *(const float4*)(srcf + q * 4);
            int cb = p * 32 + q * 4;
            Sx[r * 257 + cb] = a.x; Sx[r * 257 + cb + 1] = a.y;
            Sx[r * 257 + cb + 2] = a.z; Sx[r * 257 + cb + 3] = a.w;
            Sf[r * 257 + cb] = c.x; Sf[r * 257 + cb + 1] = c.y;
            Sf[r * 257 + cb + 2] = c.z; Sf[r * 257 + cb + 3] = c.w;
        }
    }
    __syncthreads();
    {
        int r = tid >> 3, p = tid & 7;
        float l0 = 0.f, l1 = 0.f;
#pragma unroll
        for (int cc = 0; cc < 32; ++cc) {
            int c = p * 32 + cc;
            float xv = Sx[r * 257 + c], fv = Sf[r * 257 + c];
            l0 = fmaf(xv, Wsh[c], fmaf(fv, Wsh[256 + c], l0));
            l1 = fmaf(xv, Wsh[512 + c], fmaf(fv, Wsh[768 + c], l1));
        }
#pragma unroll
        for (int o = 4; o; o >>= 1) {
            l0 += __shfl_down_sync(0xffffffffu, l0, o, 8);
            l1 += __shfl_down_sync(0xffffffffu, l1, o, 8);
        }
        if (p == 0) {
            float m = fmaxf(l0, l1);
            float e0 = expf(l0 - m), e1 = expf(l1 - m);
            float inv = 1.f / (e0 + e1);
            W0[r] = e0 * inv; W1[r] = e1 * inv;
        }
    }
    __syncthreads();
    {
        int nl = tid & 31, cg = tid >> 5;
        float w0 = W0[nl], w1 = W1[nl];
        float* o0 = out + (size_t)b * CC * NN;
        float* o1 = out + (size_t)BB * CC * NN + (size_t)b * CC * NN;
#pragma unroll
        for (int cc = 0; cc < 32; ++cc) {
            int c = cg * 32 + cc;
            float xv = Sx[nl * 257 + c], fv = Sf[nl * 257 + c];
            o0[(size_t)c * NN + n0 + nl] = fmaf(xv, w0, fv * w1);
            o1[(size_t)c * NN + n0 + nl] = fv;
        }
    }
}

// ---------------------------------------------------------------------------
extern "C" void kernel_launch(void* const* d_in, const int* in_sizes, int n_in,
                              void* d_out, int out_size) {
    const float* x = (const float*)d_in[0];
    const float* W = (const float*)d_in[1];
    float* out = (float*)d_out;

    cudaFuncSetAttribute(simargmax_kernel,
                         cudaFuncAttributeMaxDynamicSharedMemorySize, SMEM_TOTAL);
    cudaFuncSetAttribute(fuse_kernel,
                         cudaFuncAttributeMaxDynamicSharedMemorySize, FS_TOTAL);

    prep_kernel<<<dim3(NN / 32, BB), 256>>>(x);
    simargmax_kernel<<<dim3(24, BB), 512, SMEM_TOTAL>>>();
    fuse_kernel<<<dim3(NN / 32, BB), 256, FS_TOTAL>>>(W, out);
}

// round 17
// speedup vs baseline: 1.1708x; 1.1708x over previous
#include <cuda_runtime.h>
#include <cuda_fp16.h>
#include <math.h>
#include <stdint.h>

#define BB 8
#define CC 256
#define NN 2048

// tile-major pre-swizzled splits: [b][blk(16)][kc(4)][s(2)][16KB tile]
__device__ __align__(128) __half g_xs[(size_t)BB * NN * 512];
__device__ __align__(16) float g_xt[(size_t)BB * NN * CC];
__device__ unsigned long long g_key[BB * NN];

#define SWZ(o) ((o) ^ (((o) >> 3) & 0x70))
#define BLK_BYTES 131072

// 40 strips (it<<4 | jt0), <=4 tiles, sorted by strip length descending.
// Global launch order is length-sorted because blockIdx.x>>3 indexes this table.
__device__ const unsigned char g_strips[40] = {
    0x00, 0x04, 0x08, 0x0C,
    0x11, 0x15, 0x19,
    0x22, 0x26, 0x2A,
    0x33, 0x37, 0x3B,
    0x44, 0x48, 0x4C,
    0x55, 0x59,
    0x66, 0x6A,
    0x77, 0x7B,
    0x88, 0x8C,
    0x99,
    0xAA,
    0xBB,
    0xCC,
    0x1D, 0x5D, 0x9D, 0xDD,
    0x2E, 0x6E, 0xAE, 0xEE,
    0x3F, 0x7F, 0xBF, 0xFF
};

// ---------------------------------------------------------------------------
// prep: rn + f32 transpose + rn-scaled 2-way fp16 splits written tile-major
// swizzled. grid (NN/32, BB), 256 threads.
// ---------------------------------------------------------------------------
__global__ __launch_bounds__(256) void prep_kernel(const float* __restrict__ x) {
    __shared__ __half S[32][520];
    __shared__ float nsum[32][8];
    __shared__ float rns[32];
    int b = blockIdx.y, n0 = blockIdx.x * 32;
    int tid = threadIdx.x, nl = tid & 31, c8 = tid >> 5;
    const float* xp = x + (size_t)b * CC * NN + n0 + nl;

    float v[32];
    float s = 0.f;
#pragma unroll
    for (int cc = 0; cc < 32; ++cc) {
        int c = c8 * 32 + cc;
        v[cc] = xp[(size_t)c * NN];
        s = fmaf(v[cc], v[cc], s);
    }
    nsum[nl][c8] = s;
    __syncthreads();
    if (tid < 32) {
        float t = 0.f;
#pragma unroll
        for (int q = 0; q < 8; ++q) t += nsum[tid][q];
        rns[tid] = rsqrtf(t + (float)CC * 1e-6f);
    }
    __syncthreads();
    float rn = rns[nl];

    float* xt = g_xt + ((size_t)(b * NN + n0 + nl)) * 256 + c8 * 32;
#pragma unroll
    for (int q = 0; q < 8; ++q)
        *(float4*)(xt + q * 4) = make_float4(v[q * 4], v[q * 4 + 1], v[q * 4 + 2], v[q * 4 + 3]);

#pragma unroll
    for (int cc = 0; cc < 32; ++cc) {
        int c = c8 * 32 + cc;
        float f = v[cc] * rn;
        __half h1 = __float2half_rn(f);
        float r1 = f - __half2float(h1);
        __half h2 = __float2half_rn(r1);
        S[nl][c] = h1; S[nl][256 + c] = h2;
    }
    __syncthreads();

    char* outb = (char*)g_xs + (size_t)b * (NN / 128) * BLK_BYTES
               + (size_t)(n0 >> 7) * BLK_BYTES;
    int row0 = n0 & 127;
#pragma unroll
    for (int r = 0; r < 8; ++r) {
        int idx = tid + r * 256;
        int row32 = idx >> 6, c = idx & 63;
        int s2 = c >> 5, cc = c & 31;
        int kc = cc >> 3, c16 = cc & 7;
        uint4 val = *(const uint4*)&S[row32][s2 * 256 + kc * 64 + c16 * 8];
        *(uint4*)(outb + (kc * 2 + s2) * 16384 +
                  SWZ((row0 + row32) * 128 + c16 * 16)) = val;
    }
}

// ---------------------------------------------------------------------------
// smem map: A 8 tiles at 0 (128KB); ring 2x32KB at 131072; merge; bars
// ---------------------------------------------------------------------------
#define RINGOFF 131072
#define RVOFF   196608                 // [3][128] f32
#define RJOFF   198144                 // [3][128] i32
#define CVOFF   199680
#define CJOFF   201216
#define BAR_A   202752
#define BAR_R   202760
#define SMEM_TOTAL 202880

__device__ __forceinline__ void ldsm4(uint32_t* r, uint32_t saddr) {
    asm volatile("ldmatrix.sync.aligned.m8n8.x4.shared.b16 {%0,%1,%2,%3}, [%4];"
                 : "=r"(r[0]), "=r"(r[1]), "=r"(r[2]), "=r"(r[3]) : "r"(saddr));
}
__device__ __forceinline__ void mma16816f(float (&d)[4], const uint32_t (&a)[4],
                                          uint32_t b0, uint32_t b1) {
    asm volatile(
        "mma.sync.aligned.m16n8k16.row.col.f32.f16.f16.f32 "
        "{%0,%1,%2,%3},{%4,%5,%6,%7},{%8,%9},{%0,%1,%2,%3};"
        : "+f"(d[0]), "+f"(d[1]), "+f"(d[2]), "+f"(d[3])
        : "r"(a[0]), "r"(a[1]), "r"(a[2]), "r"(a[3]), "r"(b0), "r"(b1));
}
__device__ __forceinline__ void mma16816h(uint32_t (&d)[2], const uint32_t (&a)[4],
                                          uint32_t b0, uint32_t b1) {
    asm volatile(
        "mma.sync.aligned.m16n8k16.row.col.f16.f16.f16.f16 "
        "{%0,%1},{%2,%3,%4,%5},{%6,%7},{%0,%1};"
        : "+r"(d[0]), "+r"(d[1])
        : "r"(a[0]), "r"(a[1]), "r"(a[2]), "r"(a[3]), "r"(b0), "r"(b1));
}
__device__ __forceinline__ unsigned long long packKey(float v, int idx) {
    uint32_t u = __float_as_uint(v);
    uint32_t key = (u & 0x80000000u) ? ~u : (u | 0x80000000u);
    return ((unsigned long long)key << 32) | (uint32_t)(0xFFFFFFFFu - (uint32_t)idx);
}

__device__ __forceinline__ void mbar_init(uint32_t a) {
    asm volatile("mbarrier.init.shared.b64 [%0], 1;" :: "r"(a) : "memory");
}
__device__ __forceinline__ void mbar_expect(uint32_t a, uint32_t bytes) {
    asm volatile("mbarrier.arrive.expect_tx.shared.b64 _, [%0], %1;"
                 :: "r"(a), "r"(bytes) : "memory");
}
__device__ __forceinline__ void bulk_cp(uint32_t sdst, const void* gsrc,
                                        uint32_t bytes, uint32_t bar) {
    asm volatile(
        "cp.async.bulk.shared::cta.global.mbarrier::complete_tx::bytes "
        "[%0], [%1], %2, [%3];"
        :: "r"(sdst), "l"(gsrc), "r"(bytes), "r"(bar) : "memory");
}
__device__ __forceinline__ void mbar_wait(uint32_t a, uint32_t ph) {
    uint32_t done;
    do {
        asm volatile(
            "{\n\t.reg .pred p;\n\t"
            "mbarrier.try_wait.parity.acquire.cta.shared::cta.b64 p, [%1], %2, 0x989680;\n\t"
            "selp.b32 %0, 1, 0, p;\n\t}"
            : "=r"(done) : "r"(a), "r"(ph) : "memory");
    } while (!done);
}

// ---------------------------------------------------------------------------
// simargmax: triangular strips of <=4 j-tiles, GLOBALLY longest-first (1D
// grid, strip = blockIdx.x>>3, b = blockIdx.x&7). TMA bulk-copy transport,
// 512 threads = 16 warps (4M x 4N), 32x32 per-warp tile. grid (320).
// ---------------------------------------------------------------------------
__global__ __launch_bounds__(512, 1) void simargmax_kernel() {
    extern __shared__ __align__(1024) char sm[];
    const int b = blockIdx.x & 7;
    const int sv = g_strips[blockIdx.x >> 3];
    const int it = sv >> 4, jt0 = sv & 15;
    const int ntiles = min(4, 16 - jt0);
    const int i0 = it * 128;
    const int N = ntiles * 4;

    const int tid = threadIdx.x, lane = tid & 31, wid = tid >> 5;
    const int wm = wid >> 2, wn = wid & 3;
    const uint32_t smb = (uint32_t)__cvta_generic_to_shared(sm);
    const char* xsb = (const char*)g_xs + (size_t)b * 16 * BLK_BYTES;

    if (tid == 0) {
        mbar_init(smb + BAR_A);
        mbar_init(smb + BAR_R);
        mbar_init(smb + BAR_R + 8);
    }
    __syncthreads();
    if (tid == 0) {
        mbar_expect(smb + BAR_A, BLK_BYTES);
        bulk_cp(smb, xsb + (size_t)it * BLK_BYTES, BLK_BYTES, smb + BAR_A);
        mbar_expect(smb + BAR_R, 32768);
        bulk_cp(smb + RINGOFF, xsb + (size_t)jt0 * BLK_BYTES, 32768, smb + BAR_R);
    }

    const int ar0 = wm * 32 + (lane & 15);
    const int akh = lane >> 4;
    const int jr0 = wn * 32 + ((lane >> 4) & 1) * 8 + (lane & 7);
    const int bkh = (lane >> 3) & 1;

    const float NEG = __int_as_float(0xff800000);
    float rbv[4]; int rbj[4];
#pragma unroll
    for (int s = 0; s < 4; ++s) { rbv[s] = NEG; rbj[s] = 0; }

    float* Rv = (float*)(sm + RVOFF);  int* Rj = (int*)(sm + RJOFF);
    float* Cv = (float*)(sm + CVOFF);  int* Cj = (int*)(sm + CJOFF);

    for (int tile = 0; tile < ntiles; ++tile) {
        const int jt = jt0 + tile;
        const int j0 = jt * 128;
        const bool diag = (jt == it);

        float    acc[2][4][4];
        uint32_t accH[2][4][2];
#pragma unroll
        for (int mt = 0; mt < 2; ++mt)
#pragma unroll
            for (int nt = 0; nt < 4; ++nt) {
#pragma unroll
                for (int rr = 0; rr < 4; ++rr) acc[mt][nt][rr] = 0.f;
                accH[mt][nt][0] = 0u; accH[mt][nt][1] = 0u;
            }

        for (int kcc = 0; kcc < 4; ++kcc) {
            const int g = tile * 4 + kcc;
            const int slot = g & 1;
            mbar_wait(smb + BAR_R + slot * 8, (g >> 1) & 1);
            if (g == 0) mbar_wait(smb + BAR_A, 0);
            __syncthreads();
            if (tid == 0 && g + 1 < N) {
                const int g1 = g + 1;
                const int jb1 = jt0 + (g1 >> 2), kc1 = g1 & 3;
                mbar_expect(smb + BAR_R + (g1 & 1) * 8, 32768);
                bulk_cp(smb + RINGOFF + (g1 & 1) * 32768,
                        xsb + (size_t)jb1 * BLK_BYTES + kc1 * 32768,
                        32768, smb + BAR_R + (g1 & 1) * 8);
            }

#pragma unroll
            for (int ks = 0; ks < 4; ++ks) {
                uint32_t bf0[2][4], bf1[2][4];
#pragma unroll
                for (int ntp = 0; ntp < 2; ++ntp) {
                    int ro = (jr0 + ntp * 16) * 128 + (ks * 2 + bkh) * 16;
                    ldsm4(bf0[ntp], smb + RINGOFF + slot * 32768 + SWZ(ro));
                    ldsm4(bf1[ntp], smb + RINGOFF + slot * 32768 + 16384 + SWZ(ro));
                }
                uint32_t a0[2][4], a1[2][4];
#pragma unroll
                for (int mt = 0; mt < 2; ++mt) {
                    int ro = (ar0 + mt * 16) * 128 + (ks * 2 + akh) * 16;
                    ldsm4(a0[mt], smb + (kcc * 2) * 16384 + SWZ(ro));
                    ldsm4(a1[mt], smb + (kcc * 2 + 1) * 16384 + SWZ(ro));
                }
#pragma unroll
                for (int ntp = 0; ntp < 2; ++ntp) {
                    mma16816f(acc[0][ntp * 2],     a0[0], bf0[ntp][0], bf0[ntp][1]);
                    mma16816f(acc[0][ntp * 2 + 1], a0[0], bf0[ntp][2], bf0[ntp][3]);
                    mma16816f(acc[1][ntp * 2],     a0[1], bf0[ntp][0], bf0[ntp][1]);
                    mma16816f(acc[1][ntp * 2 + 1], a0[1], bf0[ntp][2], bf0[ntp][3]);
                    mma16816h(accH[0][ntp * 2],     a1[0], bf0[ntp][0], bf0[ntp][1]);
                    mma16816h(accH[0][ntp * 2 + 1], a1[0], bf0[ntp][2], bf0[ntp][3]);
                    mma16816h(accH[1][ntp * 2],     a1[1], bf0[ntp][0], bf0[ntp][1]);
                    mma16816h(accH[1][ntp * 2 + 1], a1[1], bf0[ntp][2], bf0[ntp][3]);
                    mma16816h(accH[0][ntp * 2],     a0[0], bf1[ntp][0], bf1[ntp][1]);
                    mma16816h(accH[0][ntp * 2 + 1], a0[0], bf1[ntp][2], bf1[ntp][3]);
                    mma16816h(accH[1][ntp * 2],     a0[1], bf1[ntp][0], bf1[ntp][1]);
                    mma16816h(accH[1][ntp * 2 + 1], a0[1], bf1[ntp][2], bf1[ntp][3]);
                }
            }
        }

        // ---- per-tile epilogue ----
        float cbv[8]; int cbi[8];
#pragma unroll
        for (int s = 0; s < 8; ++s) { cbv[s] = NEG; cbi[s] = 0; }

#pragma unroll
        for (int mt = 0; mt < 2; ++mt)
#pragma unroll
            for (int nt = 0; nt < 4; ++nt)
#pragma unroll
                for (int rr = 0; rr < 4; ++rr) {
                    int jl = wn * 32 + nt * 8 + (lane & 3) * 2 + (rr & 1);
                    int il = wm * 32 + mt * 16 + (rr >> 1) * 8 + (lane >> 2);
                    __half2 h2 = *(__half2*)&accH[mt][nt][rr >> 1];
                    float cross = (rr & 1) ? __high2float(h2) : __low2float(h2);
                    float v = acc[mt][nt][rr] + cross;
                    if (diag && il == jl) v = NEG;
                    int slot = mt * 2 + (rr >> 1);
                    if (v > rbv[slot]) { rbv[slot] = v; rbj[slot] = j0 + jl; }
                    int ci = nt * 2 + (rr & 1);
                    if (v > cbv[ci]) { cbv[ci] = v; cbi[ci] = il; }
                }

        if (!diag) {
#pragma unroll
            for (int ci = 0; ci < 8; ++ci) {
                float v = cbv[ci]; int i = cbi[ci];
#pragma unroll
                for (int o = 4; o <= 16; o <<= 1) {
                    float vo = __shfl_xor_sync(0xffffffffu, v, o);
                    int   io = __shfl_xor_sync(0xffffffffu, i, o);
                    if (vo > v || (vo == v && io < i)) { v = vo; i = io; }
                }
                cbv[ci] = v; cbi[ci] = i;
                if (wm > 0 && lane < 4) {
                    int col = wn * 32 + (ci >> 1) * 8 + lane * 2 + (ci & 1);
                    Cv[(wm - 1) * 128 + col] = v;
                    Cj[(wm - 1) * 128 + col] = i;
                }
            }
            __syncthreads();
            if (wm == 0 && lane < 4) {
#pragma unroll
                for (int ci = 0; ci < 8; ++ci) {
                    int col = wn * 32 + (ci >> 1) * 8 + lane * 2 + (ci & 1);
                    float v = cbv[ci]; int i = cbi[ci];
#pragma unroll
                    for (int w = 0; w < 3; ++w) {
                        float vo = Cv[w * 128 + col];
                        int   io = Cj[w * 128 + col];
                        if (vo > v || (vo == v && io < i)) { v = vo; i = io; }
                    }
                    atomicMax(&g_key[b * NN + j0 + col], packKey(v, i0 + i));
                }
            }
            __syncthreads();
        }
    }

    // ---- strip end: row reduce (quad shfl + 4 wn-warps via smem) + atomics ----
#pragma unroll
    for (int slot = 0; slot < 4; ++slot) {
        float v = rbv[slot]; int j = rbj[slot];
#pragma unroll
        for (int o = 1; o <= 2; o <<= 1) {
            float vo = __shfl_xor_sync(0xffffffffu, v, o);
            int   jo = __shfl_xor_sync(0xffffffffu, j, o);
            if (vo > v || (vo == v && jo < j)) { v = vo; j = jo; }
        }
        rbv[slot] = v; rbj[slot] = j;
        int row = wm * 32 + (slot >> 1) * 16 + (slot & 1) * 8 + (lane >> 2);
        if (wn > 0 && (lane & 3) == 0) {
            Rv[(wn - 1) * 128 + row] = v;
            Rj[(wn - 1) * 128 + row] = j;
        }
    }
    __syncthreads();
    if (wn == 0 && (lane & 3) == 0) {
#pragma unroll
        for (int slot = 0; slot < 4; ++slot) {
            int row = wm * 32 + (slot >> 1) * 16 + (slot & 1) * 8 + (lane >> 2);
            float v = rbv[slot]; int j = rbj[slot];
#pragma unroll
            for (int w = 0; w < 3; ++w) {
                float vo = Rv[w * 128 + row];
                int   jo = Rj[w * 128 + row];
                if (vo > v || (vo == v && jo < j)) { v = vo; j = jo; }
            }
            atomicMax(&g_key[b * NN + i0 + row], packKey(v, j));
        }
    }
}

// ---------------------------------------------------------------------------
// fuse
// ---------------------------------------------------------------------------
#define FS_SF 32896
#define FS_W  65792
#define FS_JI 69888
#define FS_W0 70016
#define FS_W1 70144
#define FS_TOTAL 70272

__global__ __launch_bounds__(256) void fuse_kernel(const float* __restrict__ W,
                                                   float* __restrict__ out) {
    extern __shared__ char fsm[];
    float* Sx  = (float*)fsm;
    float* Sf  = (float*)(fsm + FS_SF);
    float* Wsh = (float*)(fsm + FS_W);
    int*   Ji  = (int*)(fsm + FS_JI);
    float* W0  = (float*)(fsm + FS_W0);
    float* W1  = (float*)(fsm + FS_W1);

    int b = blockIdx.y, n0 = blockIdx.x * 32, tid = threadIdx.x;
    for (int e = tid; e < 1024; e += 256) Wsh[e] = W[e];
    if (tid < 32) {
        unsigned long long k = g_key[b * NN + n0 + tid];
        Ji[tid] = (int)(0xFFFFFFFFu - (uint32_t)(k & 0xFFFFFFFFu));
    }
    __syncthreads();

    const float* xtb = g_xt + (size_t)b * NN * 256;
    {
        int r = tid >> 3, p = tid & 7;
        const float* srcx = xtb + (size_t)(n0 + r) * 256 + p * 32;
        const float* srcf = xtb + (size_t)Ji[r] * 256 + p * 32;
#pragma unroll
        for (int q = 0; q < 8; ++q) {
            float4 a = *(const float4*)(srcx + q * 4);
            float4 c = *(const float4*)(srcf + q * 4);
            int cb = p * 32 + q * 4;
            Sx[r * 257 + cb] = a.x; Sx[r * 257 + cb + 1] = a.y;
            Sx[r * 257 + cb + 2] = a.z; Sx[r * 257 + cb + 3] = a.w;
            Sf[r * 257 + cb] = c.x; Sf[r * 257 + cb + 1] = c.y;
            Sf[r * 257 + cb + 2] = c.z; Sf[r * 257 + cb + 3] = c.w;
        }
    }
    __syncthreads();
    {
        int r = tid >> 3, p = tid & 7;
        float l0 = 0.f, l1 = 0.f;
#pragma unroll
        for (int cc = 0; cc < 32; ++cc) {
            int c = p * 32 + cc;
            float xv = Sx[r * 257 + c], fv = Sf[r * 257 + c];
            l0 = fmaf(xv, Wsh[c], fmaf(fv, Wsh[256 + c], l0));
            l1 = fmaf(xv, Wsh[512 + c], fmaf(fv, Wsh[768 + c], l1));
        }
#pragma unroll
        for (int o = 4; o; o >>= 1) {
            l0 += __shfl_down_sync(0xffffffffu, l0, o, 8);
            l1 += __shfl_down_sync(0xffffffffu, l1, o, 8);
        }
        if (p == 0) {
            float m = fmaxf(l0, l1);
            float e0 = expf(l0 - m), e1 = expf(l1 - m);
            float inv = 1.f / (e0 + e1);
            W0[r] = e0 * inv; W1[r] = e1 * inv;
        }
    }
    __syncthreads();
    {
        int nl = tid & 31, cg = tid >> 5;
        float w0 = W0[nl], w1 = W1[nl];
        float* o0 = out + (size_t)b * CC * NN;
        float* o1 = out + (size_t)BB * CC * NN + (size_t)b * CC * NN;
#pragma unroll
        for (int cc = 0; cc < 32; ++cc) {
            int c = cg * 32 + cc;
            float xv = Sx[nl * 257 + c], fv = Sf[nl * 257 + c];
            o0[(size_t)c * NN + n0 + nl] = fmaf(xv, w0, fv * w1);
            o1[(size_t)c * NN + n0 + nl] = fv;
        }
    }
}

// ---------------------------------------------------------------------------
extern "C" void kernel_launch(void* const* d_in, const int* in_sizes, int n_in,
                              void* d_out, int out_size) {
    const float* x = (const float*)d_in[0];
    const float* W = (const float*)d_in[1];
    float* out = (float*)d_out;

    cudaFuncSetAttribute(simargmax_kernel,
                         cudaFuncAttributeMaxDynamicSharedMemorySize, SMEM_TOTAL);
    cudaFuncSetAttribute(fuse_kernel,
                         cudaFuncAttributeMaxDynamicSharedMemorySize, FS_TOTAL);

    prep_kernel<<<dim3(NN / 32, BB), 256>>>(x);
    simargmax_kernel<<<320, 512, SMEM_TOTAL>>>();
    fuse_kernel<<<dim3(NN / 32, BB), 256, FS_TOTAL>>>(W, out);
}